// round 14
// baseline (speedup 1.0000x reference)
#include <cuda_runtime.h>
#include <cuda_fp16.h>
#include <cstdint>

#define NNODES 20000
#define DEG    16
#define NEDGES (NNODES * DEG)
#define NGRAPH 16
#define NPG    (NNODES / NGRAPH)   // 1250

// -------- scratch (no allocations allowed) --------
__device__ float g_x1[NNODES * 128];      // conv1 output per node
__device__ float g_y1[NNODES * 256];      // hoisted x1 @ c2_W1[0:128,:]
__device__ float g_x2[NNODES * 256];      // conv2 output per node
__device__ float g_pool[NGRAPH * 10 * 256]; // partial pooled maxima
__device__ __align__(16) __half g_w1h[128 * 128];  // c1_W2 in fp16
__device__ __align__(16) __half g_w2h[256 * 256];  // c2_W2 in fp16

// ---- packed fp32 helpers ----
__device__ __forceinline__ void addf2(unsigned long long& d, float x, float y) {
    unsigned long long s;
    asm("mov.b64 %0, {%1, %2};" : "=l"(s) : "f"(x), "f"(y));
    asm("add.rn.f32x2 %0, %0, %1;" : "+l"(d) : "l"(s));
}
__device__ __forceinline__ float lo2(unsigned long long v) {
    return __uint_as_float((unsigned)v);
}
__device__ __forceinline__ float hi2(unsigned long long v) {
    return __uint_as_float((unsigned)(v >> 32));
}

// ============================================================
// Kernel 0: prep — convert both W2 matrices to fp16 once
// ============================================================
__global__ void __launch_bounds__(256)
prep_kernel(const float* __restrict__ c1W2, const float* __restrict__ c2W2)
{
    int i = blockIdx.x * 256 + threadIdx.x;
    if (i < 16384) {
        g_w1h[i] = __float2half(c1W2[i]);
    } else {
        int j = i - 16384;
        if (j < 65536) g_w2h[j] = __float2half(c2W2[j]);
    }
}

// ============================================================
// Kernel 1: conv1 fused, fp16 HFMA2 GEMM. 128 edges/block (= 8 dsts).
// (R11 version — plain float spill)
// ============================================================
__global__ void __launch_bounds__(256, 2)
conv1_kernel(const float* __restrict__ pos, const int* __restrict__ esrc,
             const float* __restrict__ W1, const float* __restrict__ b1,
             const float* __restrict__ b2)
{
    extern __shared__ char smemc[];
    __half2* h1sT2 = (__half2*)smemc;                   // [128 k][128 e] dup pairs
    __half*  W2s   = (__half*)(smemc + 65536);          // [128 k][128 j]
    float*   A1s   = (float*)(smemc + 65536 + 32768);   // [128][8]

    const int t = threadIdx.x;

    for (int idx = t; idx < 1024; idx += 256) {
        int k = idx >> 3, j = idx & 7;
        float v = 0.f;
        if (j < 6) v = W1[j * 128 + k];
        else if (j == 6) v = b1[k];
        A1s[idx] = v;
    }
    for (int idx = t * 8; idx < 16384; idx += 2048)
        *(float4*)&W2s[idx] = *(const float4*)&g_w1h[idx];
    __syncthreads();

    // ---- phase 1: h1 (fp32 math) -> duplicated half2 ----
    const int e_local = t & 127;
    const int k0 = (t >> 7) * 64;
    const int e = blockIdx.x * 128 + e_local;
    const int s = esrc[e];
    const int d = e >> 4;                       // edge_dst = e/16 (contiguous)
    float sx = pos[s * 3 + 0], sy = pos[s * 3 + 1], sz = pos[s * 3 + 2];
    float m3 = sx - pos[d * 3 + 0];
    float m4 = sy - pos[d * 3 + 1];
    float m5 = sz - pos[d * 3 + 2];
#pragma unroll 4
    for (int k = k0; k < k0 + 64; ++k) {
        float4 a0 = *(const float4*)&A1s[k * 8];
        float4 a1 = *(const float4*)&A1s[k * 8 + 4];
        float v = a0.x * sx + a0.y * sy + a0.z * sz
                + a0.w * m3 + a1.x * m4 + a1.y * m5 + a1.z;
        h1sT2[k * 128 + e_local] = __float2half2_rn(fmaxf(v, 0.f));
    }
    __syncthreads();

    // ---- phase 2: GEMM 128x128x128 via HFMA2, 8x8 per thread ----
    const int tx = t & 15, ty = t >> 4;
    const int i0 = ty * 8, j0 = tx * 8;
    float acc_f[8][8];
#pragma unroll
    for (int i = 0; i < 8; ++i)
#pragma unroll
        for (int j = 0; j < 8; ++j) acc_f[i][j] = 0.f;

    const __half2 hz = __float2half2_rn(0.f);

#pragma unroll 1
    for (int hh = 0; hh < 8; ++hh) {        // 8 chunks x 16 k
        __half2 acc_h[8][4];
#pragma unroll
        for (int i = 0; i < 8; ++i)
#pragma unroll
            for (int jp = 0; jp < 4; ++jp) acc_h[i][jp] = hz;

#pragma unroll
        for (int kl = 0; kl < 16; ++kl) {
            int k = hh * 16 + kl;
            __half2 a2[8];
            *(float4*)&a2[0] = *(const float4*)&h1sT2[k * 128 + i0];
            *(float4*)&a2[4] = *(const float4*)&h1sT2[k * 128 + i0 + 4];
            __half2 bp[4];
            *(float4*)&bp[0] = *(const float4*)&W2s[k * 128 + j0];
#pragma unroll
            for (int i = 0; i < 8; ++i)
#pragma unroll
                for (int jp = 0; jp < 4; ++jp)
                    acc_h[i][jp] = __hfma2(a2[i], bp[jp], acc_h[i][jp]);
        }
#pragma unroll
        for (int i = 0; i < 8; ++i)
#pragma unroll
            for (int jp = 0; jp < 4; ++jp) {
                float2 f = __half22float2(acc_h[i][jp]);
                acc_f[i][2 * jp]     += f.x;
                acc_f[i][2 * jp + 1] += f.y;
            }
    }

    // ---- phase 3: 16-row segment max ----
    float pm[8];
#pragma unroll
    for (int j = 0; j < 8; ++j) {
        float m = acc_f[0][j];
#pragma unroll
        for (int i = 1; i < 8; ++i) m = fmaxf(m, acc_f[i][j]);
        pm[j] = m;
    }
    __syncthreads();            // all GEMM reads of h1sT2 done
    float* red = (float*)smemc; // reuse: [16 ty][128]
#pragma unroll
    for (int j = 0; j < 8; ++j) red[ty * 128 + j0 + j] = pm[j];
    __syncthreads();
    {
        int g = t >> 5, c0 = (t & 31) * 4;   // 8 dsts x 32 float4
        float4 r0 = *(float4*)&red[(2 * g) * 128 + c0];
        float4 r1 = *(float4*)&red[(2 * g + 1) * 128 + c0];
        float4 bb = *(const float4*)&b2[c0];
        float4 o;
        o.x = fmaxf(r0.x, r1.x) + bb.x;
        o.y = fmaxf(r0.y, r1.y) + bb.y;
        o.z = fmaxf(r0.z, r1.z) + bb.z;
        o.w = fmaxf(r0.w, r1.w) + bb.w;
        *(float4*)&g_x1[(blockIdx.x * 8 + g) * 128 + c0] = o;
    }
}

// ============================================================
// Kernel 2: y1 = x1 @ c2_W1[0:128,:]   (fp32)
// ============================================================
__global__ void __launch_bounds__(256, 1)
y1_kernel(const float* __restrict__ W)
{
    extern __shared__ float smem[];
    float* AsT = smem;
    float* Bs  = smem + 16384;
    const int t = threadIdx.x;
    const int rb = blockIdx.x * 128;
    const int cb = blockIdx.y * 128;

    {
        int i = t >> 1;
        int kk0 = (t & 1) * 64;
        int row = rb + i;
        for (int kk = kk0; kk < kk0 + 64; kk += 4) {
            float4 v = make_float4(0.f, 0.f, 0.f, 0.f);
            if (row < NNODES) v = *(const float4*)&g_x1[row * 128 + kk];
            AsT[(kk + 0) * 128 + i] = v.x;
            AsT[(kk + 1) * 128 + i] = v.y;
            AsT[(kk + 2) * 128 + i] = v.z;
            AsT[(kk + 3) * 128 + i] = v.w;
        }
    }
    for (int idx = t * 4; idx < 16384; idx += 1024) {
        int k = idx >> 7, c = idx & 127;
        *(float4*)&Bs[idx] = *(const float4*)&W[k * 256 + cb + c];
    }
    __syncthreads();

    const int tx = t & 15, ty = t >> 4;
    const int i0 = ty * 8, j0 = tx * 8;
    float acc[8][8];
#pragma unroll
    for (int i = 0; i < 8; ++i)
#pragma unroll
        for (int j = 0; j < 8; ++j) acc[i][j] = 0.f;

#pragma unroll 4
    for (int k = 0; k < 128; ++k) {
        float a[8], b[8];
        *(float4*)&a[0] = *(const float4*)&AsT[k * 128 + i0];
        *(float4*)&a[4] = *(const float4*)&AsT[k * 128 + i0 + 4];
        *(float4*)&b[0] = *(const float4*)&Bs[k * 128 + j0];
        *(float4*)&b[4] = *(const float4*)&Bs[k * 128 + j0 + 4];
#pragma unroll
        for (int i = 0; i < 8; ++i)
#pragma unroll
            for (int j = 0; j < 8; ++j)
                acc[i][j] = fmaf(a[i], b[j], acc[i][j]);
    }
#pragma unroll
    for (int i = 0; i < 8; ++i) {
        int row = rb + i0 + i;
        if (row < NNODES) {
            *(float4*)&g_y1[row * 256 + cb + j0] =
                make_float4(acc[i][0], acc[i][1], acc[i][2], acc[i][3]);
            *(float4*)&g_y1[row * 256 + cb + j0 + 4] =
                make_float4(acc[i][4], acc[i][5], acc[i][6], acc[i][7]);
        }
    }
}

// ============================================================
// Kernel 3: conv2 fused — PERSISTENT, B resident, 512 threads.
// 64-edge tiles; warp footprint 16 rows x 64 cols (4Mx8N threads,
// 4x8 per-thread tile). Per k per warp: 1 B-wavefront + 1 A-wavefront.
// smem: B 128KB + A-dup 64KB + WB 4KB = 196KB. grid=152.
// ============================================================
#define C2_NTILES (NEDGES / 64)     // 5000
__global__ void __launch_bounds__(512, 1)
conv2_kernel(const float* __restrict__ pos, const int* __restrict__ esrc,
             const float* __restrict__ c2W1, const float* __restrict__ c2b1,
             const float* __restrict__ b2)
{
    extern __shared__ char smemc[];
    __half*  Bs    = (__half*)smemc;                      // [256 k][256 j]
    __half2* h1sT2 = (__half2*)(smemc + 131072);          // [256 k][64 e] dup
    float*   WB    = (float*)(smemc + 131072 + 65536);    // 4 x 256

    const int t = threadIdx.x;
    for (int idx = t; idx < 1024; idx += 512) {
        int r = idx >> 8, c = idx & 255;
        WB[idx] = (r < 3) ? c2W1[(128 + r) * 256 + c] : c2b1[c];
    }
    // load ALL of B once: 65536 halves
    for (int idx = t * 8; idx < 65536; idx += 4096)
        *(float4*)&Bs[idx] = *(const float4*)&g_w2h[idx];

    const int e_local = t & 63;
    const int kp = (t >> 6) * 32;            // 8 partitions x 32 k
    // warp layout: 4 M-threads x 8 N-threads; warps: 4 M-groups x 4 N-groups
    const int lane = t & 31, w = t >> 5;
    const int jlane = lane & 7, ilane = lane >> 3;
    const int wN = w & 3, wM = w >> 2;
    const int i0 = wM * 16 + ilane * 4;      // 4 rows (edges)
    const int j0 = wN * 64 + jlane * 8;      // 8 cols
    const int rrow = wM * 4 + ilane;         // red row 0..15
    const __half2 hz = __float2half2_rn(0.f);
    float* red = (float*)(smemc + 131072);   // overlays A region post-GEMM

    __syncthreads();

    for (int tile = blockIdx.x; tile < C2_NTILES; tile += gridDim.x) {
        // ---- phase 1: h1 (fp32 math) -> duplicated half2 ----
        {
            const int e = tile * 64 + e_local;
            const int s = esrc[e];
            const int d = e >> 4;
            float rx = pos[s * 3 + 0] - pos[d * 3 + 0];
            float ry = pos[s * 3 + 1] - pos[d * 3 + 1];
            float rz = pos[s * 3 + 2] - pos[d * 3 + 2];
#pragma unroll 4
            for (int k = kp; k < kp + 32; k += 4) {
                float4 g4 = *(const float4*)&g_y1[s * 256 + k];
                float4 w0 = *(float4*)&WB[k];
                float4 w1 = *(float4*)&WB[256 + k];
                float4 w2 = *(float4*)&WB[512 + k];
                float4 bb = *(float4*)&WB[768 + k];
                float h0 = fmaxf(g4.x + rx * w0.x + ry * w1.x + rz * w2.x + bb.x, 0.f);
                float h1 = fmaxf(g4.y + rx * w0.y + ry * w1.y + rz * w2.y + bb.y, 0.f);
                float h2 = fmaxf(g4.z + rx * w0.z + ry * w1.z + rz * w2.z + bb.z, 0.f);
                float h3 = fmaxf(g4.w + rx * w0.w + ry * w1.w + rz * w2.w + bb.w, 0.f);
                h1sT2[(k + 0) * 64 + e_local] = __float2half2_rn(h0);
                h1sT2[(k + 1) * 64 + e_local] = __float2half2_rn(h1);
                h1sT2[(k + 2) * 64 + e_local] = __float2half2_rn(h2);
                h1sT2[(k + 3) * 64 + e_local] = __float2half2_rn(h3);
            }
        }
        __syncthreads();

        // ---- phase 2: GEMM 64x256x256 via HFMA2, 4x8 tile, no mid syncs ----
        unsigned long long acc_f2[4][4];
#pragma unroll
        for (int i = 0; i < 4; ++i)
#pragma unroll
            for (int jp = 0; jp < 4; ++jp) acc_f2[i][jp] = 0ull;

#pragma unroll 1
        for (int hh = 0; hh < 16; ++hh) {       // 16 chunks x 16 k
            __half2 acc_h[4][4];
#pragma unroll
            for (int i = 0; i < 4; ++i)
#pragma unroll
                for (int jp = 0; jp < 4; ++jp) acc_h[i][jp] = hz;

#pragma unroll
            for (int kl = 0; kl < 16; ++kl) {
                int k = hh * 16 + kl;
                __half2 a2[4];
                *(float4*)&a2[0] = *(const float4*)&h1sT2[k * 64 + i0];
                __half2 bp[4];
                *(float4*)&bp[0] = *(const float4*)&Bs[k * 256 + j0];
#pragma unroll
                for (int i = 0; i < 4; ++i)
#pragma unroll
                    for (int jp = 0; jp < 4; ++jp)
                        acc_h[i][jp] = __hfma2(a2[i], bp[jp], acc_h[i][jp]);
            }
#pragma unroll
            for (int i = 0; i < 4; ++i)
#pragma unroll
                for (int jp = 0; jp < 4; ++jp) {
                    float2 f = __half22float2(acc_h[i][jp]);
                    addf2(acc_f2[i][jp], f.x, f.y);
                }
        }

        // ---- phase 3: 16-row segment max (4 dsts per tile) ----
        float pm[8];
#pragma unroll
        for (int jp = 0; jp < 4; ++jp) {
            float ml = lo2(acc_f2[0][jp]), mh = hi2(acc_f2[0][jp]);
#pragma unroll
            for (int i = 1; i < 4; ++i) {
                ml = fmaxf(ml, lo2(acc_f2[i][jp]));
                mh = fmaxf(mh, hi2(acc_f2[i][jp]));
            }
            pm[jp * 2] = ml;
            pm[jp * 2 + 1] = mh;
        }
        __syncthreads();     // GEMM reads of h1sT2 done; red overlays it
#pragma unroll
        for (int j = 0; j < 8; ++j) red[rrow * 256 + j0 + j] = pm[j];
        __syncthreads();
        for (int idx = t; idx < 1024; idx += 512) {
            int g = idx >> 8, c = idx & 255;
            float m = red[(g * 4 + 0) * 256 + c];
            m = fmaxf(m, red[(g * 4 + 1) * 256 + c]);
            m = fmaxf(m, red[(g * 4 + 2) * 256 + c]);
            m = fmaxf(m, red[(g * 4 + 3) * 256 + c]);
            g_x2[(tile * 4 + g) * 256 + c] = m + b2[c];
        }
        __syncthreads();     // red reads done before next tile's phase1
    }
}

// ============================================================
// Kernel 4: partial global max pool
// ============================================================
__global__ void __launch_bounds__(256)
pool_kernel()
{
    const int g = blockIdx.x / 10, part = blockIdx.x % 10;
    const int c = threadIdx.x;
    const int n0 = g * NPG + part * 125;
    float m0 = -1e30f, m1 = -1e30f, m2 = -1e30f, m3 = -1e30f;
    int n = 0;
    for (; n + 4 <= 125; n += 4) {
        m0 = fmaxf(m0, g_x2[(n0 + n + 0) * 256 + c]);
        m1 = fmaxf(m1, g_x2[(n0 + n + 1) * 256 + c]);
        m2 = fmaxf(m2, g_x2[(n0 + n + 2) * 256 + c]);
        m3 = fmaxf(m3, g_x2[(n0 + n + 3) * 256 + c]);
    }
    for (; n < 125; ++n) m0 = fmaxf(m0, g_x2[(n0 + n) * 256 + c]);
    g_pool[blockIdx.x * 256 + c] = fmaxf(fmaxf(m0, m1), fmaxf(m2, m3));
}

// ============================================================
// Kernel 5: head MLP. single block.
// ============================================================
__global__ void __launch_bounds__(256)
head_kernel(const float* __restrict__ fc1W, const float* __restrict__ fc1b,
            const float* __restrict__ fc2W, const float* __restrict__ fc2b,
            const float* __restrict__ labW, const float* __restrict__ labb,
            const float* __restrict__ boxW, const float* __restrict__ boxb,
            float* __restrict__ out)
{
    __shared__ float pooled[16 * 256];
    __shared__ float h1[16 * 256];
    __shared__ float h2[16 * 128];
    const int t = threadIdx.x;

    for (int idx = t; idx < 4096; idx += 256) {
        int g = idx >> 8, c = idx & 255;
        float m = g_pool[(g * 10) * 256 + c];
#pragma unroll
        for (int p = 1; p < 10; ++p)
            m = fmaxf(m, g_pool[(g * 10 + p) * 256 + c]);
        pooled[idx] = m;
    }
    __syncthreads();

    for (int idx = t; idx < 4096; idx += 256) {
        int g = idx >> 8, c = idx & 255;
        float acc = fc1b[c];
        for (int k = 0; k < 256; ++k)
            acc = fmaf(pooled[g * 256 + k], fc1W[k * 256 + c], acc);
        h1[idx] = fmaxf(acc, 0.f);
    }
    __syncthreads();

    for (int idx = t; idx < 2048; idx += 256) {
        int g = idx >> 7, c = idx & 127;
        float acc = fc2b[c];
        for (int k = 0; k < 256; ++k)
            acc = fmaf(h1[g * 256 + k], fc2W[k * 128 + c], acc);
        h2[idx] = fmaxf(acc, 0.f);
    }
    __syncthreads();

    if (t < 160) {
        int g = t / 10, c = t % 10;
        float acc = labb[c];
        for (int k = 0; k < 128; ++k)
            acc = fmaf(h2[g * 128 + k], labW[k * 10 + c], acc);
        out[t] = acc;
    } else {
        int u = t - 160;
        int g = u / 6, c = u % 6;
        float acc = boxb[c];
        for (int k = 0; k < 128; ++k)
            acc = fmaf(h2[g * 128 + k], boxW[k * 6 + c], acc);
        out[160 + u] = acc;
    }
}

// ============================================================
extern "C" void kernel_launch(void* const* d_in, const int* in_sizes, int n_in,
                              void* d_out, int out_size)
{
    const float* pos   = (const float*)d_in[0];
    const int*   esrc  = (const int*)d_in[1];
    const float* c1W1 = (const float*)d_in[4];
    const float* c1b1 = (const float*)d_in[5];
    const float* c1W2 = (const float*)d_in[6];
    const float* c1b2 = (const float*)d_in[7];
    const float* c2W1 = (const float*)d_in[8];
    const float* c2b1 = (const float*)d_in[9];
    const float* c2W2 = (const float*)d_in[10];
    const float* c2b2 = (const float*)d_in[11];
    const float* fc1W = (const float*)d_in[12];
    const float* fc1b = (const float*)d_in[13];
    const float* fc2W = (const float*)d_in[14];
    const float* fc2b = (const float*)d_in[15];
    const float* labW = (const float*)d_in[16];
    const float* labb = (const float*)d_in[17];
    const float* boxW = (const float*)d_in[18];
    const float* boxb = (const float*)d_in[19];
    float* out = (float*)d_out;

    const int CONV1_SMEM = 65536 + 32768 + 4096;           // 102400
    const int Y1_SMEM    = 32768 * 4;                      // 131072
    const int CONV2_SMEM = 131072 + 65536 + 4096;          // 200704

    cudaFuncSetAttribute(conv1_kernel, cudaFuncAttributeMaxDynamicSharedMemorySize, CONV1_SMEM);
    cudaFuncSetAttribute(y1_kernel,    cudaFuncAttributeMaxDynamicSharedMemorySize, Y1_SMEM);
    cudaFuncSetAttribute(conv2_kernel, cudaFuncAttributeMaxDynamicSharedMemorySize, CONV2_SMEM);

    prep_kernel<<<320, 256>>>(c1W2, c2W2);
    conv1_kernel<<<NEDGES / 128, 256, CONV1_SMEM>>>(pos, esrc, c1W1, c1b1, c1b2);
    y1_kernel<<<dim3((NNODES + 127) / 128, 2), 256, Y1_SMEM>>>(c2W1);
    conv2_kernel<<<152, 512, CONV2_SMEM>>>(pos, esrc, c2W1, c2b1, c2b2);
    pool_kernel<<<160, 256>>>();
    head_kernel<<<1, 256>>>(fc1W, fc1b, fc2W, fc2b, labW, labb, boxW, boxb, out);
}

// round 15
// speedup vs baseline: 1.6039x; 1.6039x over previous
#include <cuda_runtime.h>
#include <cuda_fp16.h>
#include <cstdint>

#define NNODES 20000
#define DEG    16
#define NEDGES (NNODES * DEG)
#define NGRAPH 16
#define NPG    (NNODES / NGRAPH)   // 1250

// -------- scratch (no allocations allowed) --------
__device__ float g_x1[NNODES * 128];      // conv1 output per node
__device__ float g_y1[NNODES * 256];      // hoisted x1 @ c2_W1[0:128,:]
__device__ float g_x2[NNODES * 256];      // conv2 output per node
__device__ float g_pool[NGRAPH * 10 * 256]; // partial pooled maxima
__device__ __align__(16) __half g_w1h[128 * 128];  // c1_W2 in fp16
__device__ __align__(16) __half g_w2h[256 * 256];  // c2_W2 in fp16
__device__ __align__(16) float g_u1[NNODES * 128]; // pos@(W1a+W1b) + b1 per node
__device__ __align__(16) float g_v1[NNODES * 128]; // pos@W1b per node

// ============================================================
// Kernel 0: prep — W2 fp16 conversions + conv1 U/V hoist
// grid: 82k conversions + 640k UV elements
// ============================================================
#define PREP_CONV (16384 + 65536)                    // 81920
#define PREP_UV   (NNODES * 32)                      // 640000
__global__ void __launch_bounds__(256)
prep_kernel(const float* __restrict__ c1W2, const float* __restrict__ c2W2,
            const float* __restrict__ pos, const float* __restrict__ W1,
            const float* __restrict__ b1)
{
    int i = blockIdx.x * 256 + threadIdx.x;
    if (i < 16384) {
        g_w1h[i] = __float2half(c1W2[i]);
    } else if (i < PREP_CONV) {
        int j = i - 16384;
        g_w2h[j] = __float2half(c2W2[j]);
    } else {
        int idx = i - PREP_CONV;
        if (idx >= PREP_UV) return;
        int n = idx >> 5, q = idx & 31;
        int k = q * 4;
        float px = pos[n * 3 + 0], py = pos[n * 3 + 1], pz = pos[n * 3 + 2];
        float4 u, v;
        {
            float w0 = W1[0 * 128 + k], w1 = W1[1 * 128 + k], w2 = W1[2 * 128 + k];
            float w3 = W1[3 * 128 + k], w4 = W1[4 * 128 + k], w5 = W1[5 * 128 + k];
            v.x = px * w3 + py * w4 + pz * w5;
            u.x = px * (w0 + w3) + py * (w1 + w4) + pz * (w2 + w5) + b1[k];
        }
        {
            float w0 = W1[0 * 128 + k + 1], w1 = W1[1 * 128 + k + 1], w2 = W1[2 * 128 + k + 1];
            float w3 = W1[3 * 128 + k + 1], w4 = W1[4 * 128 + k + 1], w5 = W1[5 * 128 + k + 1];
            v.y = px * w3 + py * w4 + pz * w5;
            u.y = px * (w0 + w3) + py * (w1 + w4) + pz * (w2 + w5) + b1[k + 1];
        }
        {
            float w0 = W1[0 * 128 + k + 2], w1 = W1[1 * 128 + k + 2], w2 = W1[2 * 128 + k + 2];
            float w3 = W1[3 * 128 + k + 2], w4 = W1[4 * 128 + k + 2], w5 = W1[5 * 128 + k + 2];
            v.z = px * w3 + py * w4 + pz * w5;
            u.z = px * (w0 + w3) + py * (w1 + w4) + pz * (w2 + w5) + b1[k + 2];
        }
        {
            float w0 = W1[0 * 128 + k + 3], w1 = W1[1 * 128 + k + 3], w2 = W1[2 * 128 + k + 3];
            float w3 = W1[3 * 128 + k + 3], w4 = W1[4 * 128 + k + 3], w5 = W1[5 * 128 + k + 3];
            v.w = px * w3 + py * w4 + pz * w5;
            u.w = px * (w0 + w3) + py * (w1 + w4) + pz * (w2 + w5) + b1[k + 3];
        }
        *(float4*)&g_u1[n * 128 + k] = u;
        *(float4*)&g_v1[n * 128 + k] = v;
    }
}

// ============================================================
// Kernel 1: conv1 fused, fp16 HFMA2 GEMM. 128 edges/block (= 8 dsts).
// phase1 via U/V hoist: h1 = relu(U[s] - V[d])
// smem: h1sT2 64KB + W2h 32KB = 96KB, 2 blocks/SM
// ============================================================
__global__ void __launch_bounds__(256, 2)
conv1_kernel(const int* __restrict__ esrc, const float* __restrict__ b2)
{
    extern __shared__ char smemc[];
    __half2* h1sT2 = (__half2*)smemc;                   // [128 k][128 e] dup pairs
    __half*  W2s   = (__half*)(smemc + 65536);          // [128 k][128 j]

    const int t = threadIdx.x;

    for (int idx = t * 8; idx < 16384; idx += 2048)
        *(float4*)&W2s[idx] = *(const float4*)&g_w1h[idx];

    // ---- phase 1: h1 = relu(U[s]-V[d]) -> duplicated half2 ----
    const int e_local = t & 127;
    const int k0 = (t >> 7) * 64;
    const int e = blockIdx.x * 128 + e_local;
    const int s = esrc[e];
    const int d = e >> 4;                       // edge_dst = e/16 (contiguous)
    const float4* Urow = (const float4*)&g_u1[s * 128];
    const float4* Vrow = (const float4*)&g_v1[d * 128];
#pragma unroll 4
    for (int k = k0; k < k0 + 64; k += 4) {
        float4 u = Urow[k >> 2];
        float4 v = Vrow[k >> 2];
        h1sT2[(k + 0) * 128 + e_local] = __float2half2_rn(fmaxf(u.x - v.x, 0.f));
        h1sT2[(k + 1) * 128 + e_local] = __float2half2_rn(fmaxf(u.y - v.y, 0.f));
        h1sT2[(k + 2) * 128 + e_local] = __float2half2_rn(fmaxf(u.z - v.z, 0.f));
        h1sT2[(k + 3) * 128 + e_local] = __float2half2_rn(fmaxf(u.w - v.w, 0.f));
    }
    __syncthreads();

    // ---- phase 2: GEMM 128x128x128 via HFMA2, 8x8 per thread ----
    const int tx = t & 15, ty = t >> 4;
    const int i0 = ty * 8, j0 = tx * 8;
    float acc_f[8][8];
#pragma unroll
    for (int i = 0; i < 8; ++i)
#pragma unroll
        for (int j = 0; j < 8; ++j) acc_f[i][j] = 0.f;

    const __half2 hz = __float2half2_rn(0.f);

#pragma unroll 1
    for (int hh = 0; hh < 8; ++hh) {        // 8 chunks x 16 k
        __half2 acc_h[8][4];
#pragma unroll
        for (int i = 0; i < 8; ++i)
#pragma unroll
            for (int jp = 0; jp < 4; ++jp) acc_h[i][jp] = hz;

#pragma unroll
        for (int kl = 0; kl < 16; ++kl) {
            int k = hh * 16 + kl;
            __half2 a2[8];
            *(float4*)&a2[0] = *(const float4*)&h1sT2[k * 128 + i0];
            *(float4*)&a2[4] = *(const float4*)&h1sT2[k * 128 + i0 + 4];
            __half2 bp[4];
            *(float4*)&bp[0] = *(const float4*)&W2s[k * 128 + j0];
#pragma unroll
            for (int i = 0; i < 8; ++i)
#pragma unroll
                for (int jp = 0; jp < 4; ++jp)
                    acc_h[i][jp] = __hfma2(a2[i], bp[jp], acc_h[i][jp]);
        }
#pragma unroll
        for (int i = 0; i < 8; ++i)
#pragma unroll
            for (int jp = 0; jp < 4; ++jp) {
                float2 f = __half22float2(acc_h[i][jp]);
                acc_f[i][2 * jp]     += f.x;
                acc_f[i][2 * jp + 1] += f.y;
            }
    }

    // ---- phase 3: 16-row segment max ----
    float pm[8];
#pragma unroll
    for (int j = 0; j < 8; ++j) {
        float m = acc_f[0][j];
#pragma unroll
        for (int i = 1; i < 8; ++i) m = fmaxf(m, acc_f[i][j]);
        pm[j] = m;
    }
    __syncthreads();            // all GEMM reads of h1sT2 done
    float* red = (float*)smemc; // reuse: [16 ty][128]
#pragma unroll
    for (int j = 0; j < 8; ++j) red[ty * 128 + j0 + j] = pm[j];
    __syncthreads();
    {
        int g = t >> 5, c0 = (t & 31) * 4;   // 8 dsts x 32 float4
        float4 r0 = *(float4*)&red[(2 * g) * 128 + c0];
        float4 r1 = *(float4*)&red[(2 * g + 1) * 128 + c0];
        float4 bb = *(const float4*)&b2[c0];
        float4 o;
        o.x = fmaxf(r0.x, r1.x) + bb.x;
        o.y = fmaxf(r0.y, r1.y) + bb.y;
        o.z = fmaxf(r0.z, r1.z) + bb.z;
        o.w = fmaxf(r0.w, r1.w) + bb.w;
        *(float4*)&g_x1[(blockIdx.x * 8 + g) * 128 + c0] = o;
    }
}

// ============================================================
// Kernel 2: y1 = x1 @ c2_W1[0:128,:]   (fp32)
// ============================================================
__global__ void __launch_bounds__(256, 1)
y1_kernel(const float* __restrict__ W)
{
    extern __shared__ float smem[];
    float* AsT = smem;
    float* Bs  = smem + 16384;
    const int t = threadIdx.x;
    const int rb = blockIdx.x * 128;
    const int cb = blockIdx.y * 128;

    {
        int i = t >> 1;
        int kk0 = (t & 1) * 64;
        int row = rb + i;
        for (int kk = kk0; kk < kk0 + 64; kk += 4) {
            float4 v = make_float4(0.f, 0.f, 0.f, 0.f);
            if (row < NNODES) v = *(const float4*)&g_x1[row * 128 + kk];
            AsT[(kk + 0) * 128 + i] = v.x;
            AsT[(kk + 1) * 128 + i] = v.y;
            AsT[(kk + 2) * 128 + i] = v.z;
            AsT[(kk + 3) * 128 + i] = v.w;
        }
    }
    for (int idx = t * 4; idx < 16384; idx += 1024) {
        int k = idx >> 7, c = idx & 127;
        *(float4*)&Bs[idx] = *(const float4*)&W[k * 256 + cb + c];
    }
    __syncthreads();

    const int tx = t & 15, ty = t >> 4;
    const int i0 = ty * 8, j0 = tx * 8;
    float acc[8][8];
#pragma unroll
    for (int i = 0; i < 8; ++i)
#pragma unroll
        for (int j = 0; j < 8; ++j) acc[i][j] = 0.f;

#pragma unroll 4
    for (int k = 0; k < 128; ++k) {
        float a[8], b[8];
        *(float4*)&a[0] = *(const float4*)&AsT[k * 128 + i0];
        *(float4*)&a[4] = *(const float4*)&AsT[k * 128 + i0 + 4];
        *(float4*)&b[0] = *(const float4*)&Bs[k * 128 + j0];
        *(float4*)&b[4] = *(const float4*)&Bs[k * 128 + j0 + 4];
#pragma unroll
        for (int i = 0; i < 8; ++i)
#pragma unroll
            for (int j = 0; j < 8; ++j)
                acc[i][j] = fmaf(a[i], b[j], acc[i][j]);
    }
#pragma unroll
    for (int i = 0; i < 8; ++i) {
        int row = rb + i0 + i;
        if (row < NNODES) {
            *(float4*)&g_y1[row * 256 + cb + j0] =
                make_float4(acc[i][0], acc[i][1], acc[i][2], acc[i][3]);
            *(float4*)&g_y1[row * 256 + cb + j0 + 4] =
                make_float4(acc[i][4], acc[i][5], acc[i][6], acc[i][7]);
        }
    }
}

// ============================================================
// Kernel 3: conv2 fused — PERSISTENT (R11 shape: 256 thr, 64-edge
// tiles, 8x8 per-thread), B resident, dedicated red buffer
// -> 2 syncs/tile.
// smem: B 128KB + A-dup 64KB + WB 4KB + red 8KB = 204KB. grid=152.
// ============================================================
#define C2_NTILES (NEDGES / 64)     // 5000
__global__ void __launch_bounds__(256, 1)
conv2_kernel(const float* __restrict__ pos, const int* __restrict__ esrc,
             const float* __restrict__ c2W1, const float* __restrict__ c2b1,
             const float* __restrict__ b2)
{
    extern __shared__ char smemc[];
    __half*  Bs    = (__half*)smemc;                      // [256 k][256 j]
    __half2* h1sT2 = (__half2*)(smemc + 131072);          // [256 k][64 e] dup
    float*   WB    = (float*)(smemc + 131072 + 65536);    // 4 x 256
    float*   red   = (float*)(smemc + 131072 + 65536 + 4096); // [8][256]

    const int t = threadIdx.x;
    {
        int c = t;
        WB[c]       = c2W1[128 * 256 + c];
        WB[256 + c] = c2W1[129 * 256 + c];
        WB[512 + c] = c2W1[130 * 256 + c];
        WB[768 + c] = c2b1[c];
    }
    // load ALL of B once: 65536 halves
    for (int idx = t * 8; idx < 65536; idx += 2048)
        *(float4*)&Bs[idx] = *(const float4*)&g_w2h[idx];

    const int e_local = t & 63;
    const int k0 = (t >> 6) * 64;
    const int ty = t >> 5, tx = t & 31;
    const int i0 = ty * 8, j0 = tx * 8;
    const __half2 hz = __float2half2_rn(0.f);

    __syncthreads();

    for (int tile = blockIdx.x; tile < C2_NTILES; tile += gridDim.x) {
        // ---- phase 1: h1 (fp32 math) -> duplicated half2 ----
        {
            const int e = tile * 64 + e_local;
            const int s = esrc[e];
            const int d = e >> 4;
            float rx = pos[s * 3 + 0] - pos[d * 3 + 0];
            float ry = pos[s * 3 + 1] - pos[d * 3 + 1];
            float rz = pos[s * 3 + 2] - pos[d * 3 + 2];
#pragma unroll 4
            for (int k = k0; k < k0 + 64; k += 4) {
                float4 g4 = *(const float4*)&g_y1[s * 256 + k];
                float4 w0 = *(float4*)&WB[k];
                float4 w1 = *(float4*)&WB[256 + k];
                float4 w2 = *(float4*)&WB[512 + k];
                float4 bb = *(float4*)&WB[768 + k];
                float h0 = fmaxf(g4.x + rx * w0.x + ry * w1.x + rz * w2.x + bb.x, 0.f);
                float h1 = fmaxf(g4.y + rx * w0.y + ry * w1.y + rz * w2.y + bb.y, 0.f);
                float h2 = fmaxf(g4.z + rx * w0.z + ry * w1.z + rz * w2.z + bb.z, 0.f);
                float h3 = fmaxf(g4.w + rx * w0.w + ry * w1.w + rz * w2.w + bb.w, 0.f);
                h1sT2[(k + 0) * 64 + e_local] = __float2half2_rn(h0);
                h1sT2[(k + 1) * 64 + e_local] = __float2half2_rn(h1);
                h1sT2[(k + 2) * 64 + e_local] = __float2half2_rn(h2);
                h1sT2[(k + 3) * 64 + e_local] = __float2half2_rn(h3);
            }
        }
        __syncthreads();     // (a) h1sT2 writes -> GEMM reads

        // ---- phase 2: GEMM 64x256x256 via HFMA2, 8x8 tile, no mid syncs ----
        float acc_f[8][8];
#pragma unroll
        for (int i = 0; i < 8; ++i)
#pragma unroll
            for (int j = 0; j < 8; ++j) acc_f[i][j] = 0.f;

#pragma unroll 1
        for (int hh = 0; hh < 16; ++hh) {       // 16 chunks x 16 k
            __half2 acc_h[8][4];
#pragma unroll
            for (int i = 0; i < 8; ++i)
#pragma unroll
                for (int jp = 0; jp < 4; ++jp) acc_h[i][jp] = hz;

#pragma unroll
            for (int kl = 0; kl < 16; ++kl) {
                int k = hh * 16 + kl;
                __half2 a2[8];
                *(float4*)&a2[0] = *(const float4*)&h1sT2[k * 64 + i0];
                *(float4*)&a2[4] = *(const float4*)&h1sT2[k * 64 + i0 + 4];
                __half2 bp[4];
                *(float4*)&bp[0] = *(const float4*)&Bs[k * 256 + j0];
#pragma unroll
                for (int i = 0; i < 8; ++i)
#pragma unroll
                    for (int jp = 0; jp < 4; ++jp)
                        acc_h[i][jp] = __hfma2(a2[i], bp[jp], acc_h[i][jp]);
            }
#pragma unroll
            for (int i = 0; i < 8; ++i)
#pragma unroll
                for (int jp = 0; jp < 4; ++jp) {
                    float2 f = __half22float2(acc_h[i][jp]);
                    acc_f[i][2 * jp]     += f.x;
                    acc_f[i][2 * jp + 1] += f.y;
                }
        }

        // ---- phase 3: 16-row segment max (4 dsts per tile) ----
        float pm[8];
#pragma unroll
        for (int j = 0; j < 8; ++j) {
            float m = acc_f[0][j];
#pragma unroll
            for (int i = 1; i < 8; ++i) m = fmaxf(m, acc_f[i][j]);
            pm[j] = m;
        }
        // dedicated red buffer: each thread writes its own rows, no pre-sync
#pragma unroll
        for (int j = 0; j < 8; ++j) red[ty * 256 + j0 + j] = pm[j];
        __syncthreads();     // (c) red writes -> red reads; also GEMM done
        {
            int g = t >> 6, c0 = (t & 63) * 4;   // 4 dsts x 64 float4
            float4 r0 = *(float4*)&red[(2 * g) * 256 + c0];
            float4 r1 = *(float4*)&red[(2 * g + 1) * 256 + c0];
            float4 bb = *(const float4*)&b2[c0];
            float4 o;
            o.x = fmaxf(r0.x, r1.x) + bb.x;
            o.y = fmaxf(r0.y, r1.y) + bb.y;
            o.z = fmaxf(r0.z, r1.z) + bb.z;
            o.w = fmaxf(r0.w, r1.w) + bb.w;
            *(float4*)&g_x2[(tile * 4 + g) * 256 + c0] = o;
        }
        // no trailing sync: red reads complete before this thread's next
        // sync (a); next red writes happen only after all pass sync (a).
    }
}

// ============================================================
// Kernel 4: partial global max pool
// ============================================================
__global__ void __launch_bounds__(256)
pool_kernel()
{
    const int g = blockIdx.x / 10, part = blockIdx.x % 10;
    const int c = threadIdx.x;
    const int n0 = g * NPG + part * 125;
    float m0 = -1e30f, m1 = -1e30f, m2 = -1e30f, m3 = -1e30f;
    int n = 0;
    for (; n + 4 <= 125; n += 4) {
        m0 = fmaxf(m0, g_x2[(n0 + n + 0) * 256 + c]);
        m1 = fmaxf(m1, g_x2[(n0 + n + 1) * 256 + c]);
        m2 = fmaxf(m2, g_x2[(n0 + n + 2) * 256 + c]);
        m3 = fmaxf(m3, g_x2[(n0 + n + 3) * 256 + c]);
    }
    for (; n < 125; ++n) m0 = fmaxf(m0, g_x2[(n0 + n) * 256 + c]);
    g_pool[blockIdx.x * 256 + c] = fmaxf(fmaxf(m0, m1), fmaxf(m2, m3));
}

// ============================================================
// Kernel 5: head MLP. single block.
// ============================================================
__global__ void __launch_bounds__(256)
head_kernel(const float* __restrict__ fc1W, const float* __restrict__ fc1b,
            const float* __restrict__ fc2W, const float* __restrict__ fc2b,
            const float* __restrict__ labW, const float* __restrict__ labb,
            const float* __restrict__ boxW, const float* __restrict__ boxb,
            float* __restrict__ out)
{
    __shared__ float pooled[16 * 256];
    __shared__ float h1[16 * 256];
    __shared__ float h2[16 * 128];
    const int t = threadIdx.x;

    for (int idx = t; idx < 4096; idx += 256) {
        int g = idx >> 8, c = idx & 255;
        float m = g_pool[(g * 10) * 256 + c];
#pragma unroll
        for (int p = 1; p < 10; ++p)
            m = fmaxf(m, g_pool[(g * 10 + p) * 256 + c]);
        pooled[idx] = m;
    }
    __syncthreads();

    for (int idx = t; idx < 4096; idx += 256) {
        int g = idx >> 8, c = idx & 255;
        float acc = fc1b[c];
        for (int k = 0; k < 256; ++k)
            acc = fmaf(pooled[g * 256 + k], fc1W[k * 256 + c], acc);
        h1[idx] = fmaxf(acc, 0.f);
    }
    __syncthreads();

    for (int idx = t; idx < 2048; idx += 256) {
        int g = idx >> 7, c = idx & 127;
        float acc = fc2b[c];
        for (int k = 0; k < 256; ++k)
            acc = fmaf(h1[g * 256 + k], fc2W[k * 128 + c], acc);
        h2[idx] = fmaxf(acc, 0.f);
    }
    __syncthreads();

    if (t < 160) {
        int g = t / 10, c = t % 10;
        float acc = labb[c];
        for (int k = 0; k < 128; ++k)
            acc = fmaf(h2[g * 128 + k], labW[k * 10 + c], acc);
        out[t] = acc;
    } else {
        int u = t - 160;
        int g = u / 6, c = u % 6;
        float acc = boxb[c];
        for (int k = 0; k < 128; ++k)
            acc = fmaf(h2[g * 128 + k], boxW[k * 6 + c], acc);
        out[160 + u] = acc;
    }
}

// ============================================================
extern "C" void kernel_launch(void* const* d_in, const int* in_sizes, int n_in,
                              void* d_out, int out_size)
{
    const float* pos   = (const float*)d_in[0];
    const int*   esrc  = (const int*)d_in[1];
    const float* c1W1 = (const float*)d_in[4];
    const float* c1b1 = (const float*)d_in[5];
    const float* c1W2 = (const float*)d_in[6];
    const float* c1b2 = (const float*)d_in[7];
    const float* c2W1 = (const float*)d_in[8];
    const float* c2b1 = (const float*)d_in[9];
    const float* c2W2 = (const float*)d_in[10];
    const float* c2b2 = (const float*)d_in[11];
    const float* fc1W = (const float*)d_in[12];
    const float* fc1b = (const float*)d_in[13];
    const float* fc2W = (const float*)d_in[14];
    const float* fc2b = (const float*)d_in[15];
    const float* labW = (const float*)d_in[16];
    const float* labb = (const float*)d_in[17];
    const float* boxW = (const float*)d_in[18];
    const float* boxb = (const float*)d_in[19];
    float* out = (float*)d_out;

    const int CONV1_SMEM = 65536 + 32768;                          // 98304
    const int Y1_SMEM    = 32768 * 4;                              // 131072
    const int CONV2_SMEM = 131072 + 65536 + 4096 + 8192;           // 208896

    cudaFuncSetAttribute(conv1_kernel, cudaFuncAttributeMaxDynamicSharedMemorySize, CONV1_SMEM);
    cudaFuncSetAttribute(y1_kernel,    cudaFuncAttributeMaxDynamicSharedMemorySize, Y1_SMEM);
    cudaFuncSetAttribute(conv2_kernel, cudaFuncAttributeMaxDynamicSharedMemorySize, CONV2_SMEM);

    const int prep_blocks = (PREP_CONV + PREP_UV + 255) / 256;     // 2820
    prep_kernel<<<prep_blocks, 256>>>(c1W2, c2W2, pos, c1W1, c1b1);
    conv1_kernel<<<NEDGES / 128, 256, CONV1_SMEM>>>(esrc, c1b2);
    y1_kernel<<<dim3((NNODES + 127) / 128, 2), 256, Y1_SMEM>>>(c2W1);
    conv2_kernel<<<152, 256, CONV2_SMEM>>>(pos, esrc, c2W1, c2b1, c2b2);
    pool_kernel<<<160, 256>>>();
    head_kernel<<<1, 256>>>(fc1W, fc1b, fc2W, fc2b, labW, labb, boxW, boxb, out);
}